// round 6
// baseline (speedup 1.0000x reference)
#include <cuda_runtime.h>
#include <math.h>

#define BB   8
#define NCELL 1024
#define SLEN 1025
#define D    256
#define NH   8
#define HD   32
#define DFF  1024
#define NL   4
#define MTOK (BB*SLEN)   // 8200

// ---------------- scratch (static device globals; no allocs) ----------------
__device__ float g_x[MTOK*D];
__device__ float g_q[MTOK*D];
__device__ float g_k[MTOK*D];
__device__ float g_v[MTOK*D];
__device__ float g_a[MTOK*D];
__device__ float g_t[MTOK*D];
__device__ float g_h[(size_t)MTOK*DFF];

// ---------------- embedding: emb + cell-type MLP + positional + cls ----------
__global__ void embed_kernel(const float* __restrict__ cf,
                             const int* __restrict__ xc,
                             const int* __restrict__ yc,
                             const float* __restrict__ Wemb,
                             const float* __restrict__ bemb,
                             const float* __restrict__ Wct1,
                             const float* __restrict__ bct1,
                             const float* __restrict__ Wct2,
                             const float* __restrict__ bct2,
                             const float* __restrict__ cls)
{
    int blk = blockIdx.x;          // 0..8199
    int b = blk / SLEN;
    int s = blk % SLEN;
    int d = threadIdx.x;           // 0..255
    float* out = g_x + (size_t)blk * D;

    if (s == 0) { out[d] = cls[d]; return; }
    int n = s - 1;

    __shared__ float cfs[64];
    __shared__ float hs[128];
    const float* cfp = cf + ((size_t)b*NCELL + n)*64;
    if (d < 64) cfs[d] = cfp[d];
    __syncthreads();

    if (d < 128) {
        float acc = bct1[d];
        #pragma unroll
        for (int k = 0; k < 64; k++) acc = fmaf(cfs[k], Wct1[k*128 + d], acc);
        hs[d] = fmaxf(acc, 0.f);
    }
    __syncthreads();

    float e = bemb[d];
    #pragma unroll
    for (int k = 0; k < 64; k++) e = fmaf(cfs[k], Wemb[k*256 + d], e);
    float c2 = bct2[d];
    #pragma unroll
    for (int j = 0; j < 128; j++) c2 = fmaf(hs[j], Wct2[j*256 + d], c2);

    // positional encoding (match jax: div = exp(2m * (-ln(10000)/128)))
    int dd    = (d < 128) ? d : d - 128;
    int coord = (d < 128) ? xc[b*NCELL + n] : yc[b*NCELL + n];
    coord = min(max(coord, 0), 999);
    int m = dd >> 1;
    const float c1 = -0.07195578739046225f;  // float(-ln(10000)/128)
    float dv  = expf((float)(2*m) * c1);
    float ang = (float)coord * dv;
    float p   = (dd & 1) ? cosf(ang) : sinf(ang);

    out[d] = e + c2 + p;
}

// ---------------- generic tiled SGEMM: C = A(MxK) @ W(KxN) + bias [ReLU] -----
__global__ void gemm_kernel(const float* __restrict__ A,
                            const float* __restrict__ W,
                            const float* __restrict__ bias,
                            float* __restrict__ C,
                            int M, int N, int K, int relu)
{
    __shared__ float As[32][65];   // transposed A tile, padded
    __shared__ float Bs[32][64];

    int tid = threadIdx.x;
    int m0 = blockIdx.x * 64;
    int n0 = blockIdx.y * 64;
    int r0 = (tid >> 4) << 2;      // 0..60
    int c0 = (tid & 15) << 2;      // 0..60

    float acc[4][4] = {};

    for (int k0 = 0; k0 < K; k0 += 32) {
        #pragma unroll
        for (int i = 0; i < 2; i++) {
            int idx = tid + i*256;
            // A tile: 64 rows x 32 k, float4 along K, store transposed
            int arow = idx >> 3;
            int kc   = (idx & 7) << 2;
            float4 va = make_float4(0.f,0.f,0.f,0.f);
            int gr = m0 + arow;
            if (gr < M) va = *(const float4*)(A + (size_t)gr*K + (k0 + kc));
            As[kc+0][arow] = va.x; As[kc+1][arow] = va.y;
            As[kc+2][arow] = va.z; As[kc+3][arow] = va.w;
            // B tile: 32 k rows x 64 n
            int brow = idx >> 4;
            int bc   = (idx & 15) << 2;
            *(float4*)&Bs[brow][bc] =
                *(const float4*)(W + (size_t)(k0 + brow)*N + (n0 + bc));
        }
        __syncthreads();

        #pragma unroll
        for (int kk = 0; kk < 32; kk++) {
            float a0 = As[kk][r0+0], a1 = As[kk][r0+1];
            float a2 = As[kk][r0+2], a3 = As[kk][r0+3];
            float4 bv = *(const float4*)&Bs[kk][c0];
            acc[0][0] = fmaf(a0, bv.x, acc[0][0]); acc[0][1] = fmaf(a0, bv.y, acc[0][1]);
            acc[0][2] = fmaf(a0, bv.z, acc[0][2]); acc[0][3] = fmaf(a0, bv.w, acc[0][3]);
            acc[1][0] = fmaf(a1, bv.x, acc[1][0]); acc[1][1] = fmaf(a1, bv.y, acc[1][1]);
            acc[1][2] = fmaf(a1, bv.z, acc[1][2]); acc[1][3] = fmaf(a1, bv.w, acc[1][3]);
            acc[2][0] = fmaf(a2, bv.x, acc[2][0]); acc[2][1] = fmaf(a2, bv.y, acc[2][1]);
            acc[2][2] = fmaf(a2, bv.z, acc[2][2]); acc[2][3] = fmaf(a2, bv.w, acc[2][3]);
            acc[3][0] = fmaf(a3, bv.x, acc[3][0]); acc[3][1] = fmaf(a3, bv.y, acc[3][1]);
            acc[3][2] = fmaf(a3, bv.z, acc[3][2]); acc[3][3] = fmaf(a3, bv.w, acc[3][3]);
        }
        __syncthreads();
    }

    float4 bb = *(const float4*)(bias + n0 + c0);
    float bvv[4] = {bb.x, bb.y, bb.z, bb.w};
    #pragma unroll
    for (int r = 0; r < 4; r++) {
        int gr = m0 + r0 + r;
        if (gr < M) {
            float4 o;
            o.x = acc[r][0] + bvv[0];
            o.y = acc[r][1] + bvv[1];
            o.z = acc[r][2] + bvv[2];
            o.w = acc[r][3] + bvv[3];
            if (relu) {
                o.x = fmaxf(o.x, 0.f); o.y = fmaxf(o.y, 0.f);
                o.z = fmaxf(o.z, 0.f); o.w = fmaxf(o.w, 0.f);
            }
            *(float4*)(C + (size_t)gr*N + n0 + c0) = o;
        }
    }
}

// ---------------- flash attention per (q-tile, head, batch) ------------------
__global__ void attn_kernel()
{
    int qt = blockIdx.x;           // 0..16
    int h  = blockIdx.y;
    int b  = blockIdx.z;
    int tid = threadIdx.x;
    int rl  = tid >> 2;            // 0..63 local q row
    int sub = tid & 3;             // 0..3, 16 k-cols each
    int qrow = qt*64 + rl;
    bool qvalid = qrow < SLEN;

    const float scale = 0.17677669529663687f;   // 1/sqrt(32)
    const float* qbase = g_q + (size_t)(b*SLEN)*D + h*HD;
    const float* kbase = g_k + (size_t)(b*SLEN)*D + h*HD;
    const float* vbase = g_v + (size_t)(b*SLEN)*D + h*HD;

    float q[HD];
    #pragma unroll
    for (int d = 0; d < HD; d++)
        q[d] = qvalid ? qbase[(size_t)qrow*D + d] * scale : 0.f;

    __shared__ float ks[64][33];
    __shared__ float vs[64][33];

    float m = -INFINITY, l = 0.f;
    float acc[HD];
    #pragma unroll
    for (int d = 0; d < HD; d++) acc[d] = 0.f;

    const int ntiles = (SLEN + 63) / 64;   // 17
    for (int t = 0; t < ntiles; t++) {
        int k0 = t*64;
        __syncthreads();
        #pragma unroll
        for (int i = 0; i < 2; i++) {
            int idx = tid + i*256;         // float4 index, 0..511
            int row = idx >> 3;
            int c4  = (idx & 7) << 2;
            float4 kv = make_float4(0.f,0.f,0.f,0.f);
            float4 vv = make_float4(0.f,0.f,0.f,0.f);
            int gk = k0 + row;
            if (gk < SLEN) {
                kv = *(const float4*)(kbase + (size_t)gk*D + c4);
                vv = *(const float4*)(vbase + (size_t)gk*D + c4);
            }
            ks[row][c4+0]=kv.x; ks[row][c4+1]=kv.y; ks[row][c4+2]=kv.z; ks[row][c4+3]=kv.w;
            vs[row][c4+0]=vv.x; vs[row][c4+1]=vv.y; vs[row][c4+2]=vv.z; vs[row][c4+3]=vv.w;
        }
        __syncthreads();

        int jbase = sub * 16;
        float p[16];
        float tmax = -INFINITY;
        #pragma unroll
        for (int j = 0; j < 16; j++) {
            int col = k0 + jbase + j;
            float s = -INFINITY;
            if (col < SLEN) {
                s = 0.f;
                #pragma unroll
                for (int d = 0; d < HD; d++)
                    s = fmaf(q[d], ks[jbase+j][d], s);
            }
            p[j] = s;
            tmax = fmaxf(tmax, s);
        }
        tmax = fmaxf(tmax, __shfl_xor_sync(0xffffffffu, tmax, 1));
        tmax = fmaxf(tmax, __shfl_xor_sync(0xffffffffu, tmax, 2));

        float mnew = fmaxf(m, tmax);
        float corr = expf(m - mnew);       // first tile: exp(-inf)=0
        l *= corr;
        #pragma unroll
        for (int d = 0; d < HD; d++) acc[d] *= corr;

        float ls = 0.f;
        #pragma unroll
        for (int j = 0; j < 16; j++) {
            p[j] = expf(p[j] - mnew);      // -inf -> 0
            ls += p[j];
        }
        l += ls;

        #pragma unroll
        for (int j = 0; j < 16; j++) {
            float pj = p[j];
            #pragma unroll
            for (int d = 0; d < HD; d++)
                acc[d] = fmaf(pj, vs[jbase+j][d], acc[d]);
        }
        m = mnew;
    }

    // reduce across the 4 sub-threads of each row
    l += __shfl_xor_sync(0xffffffffu, l, 1);
    l += __shfl_xor_sync(0xffffffffu, l, 2);
    #pragma unroll
    for (int d = 0; d < HD; d++) {
        acc[d] += __shfl_xor_sync(0xffffffffu, acc[d], 1);
        acc[d] += __shfl_xor_sync(0xffffffffu, acc[d], 2);
    }

    if (qvalid && sub == 0) {
        float inv = 1.f / l;
        float* outp = g_a + (size_t)(b*SLEN + qrow)*D + h*HD;
        #pragma unroll
        for (int d = 0; d < HD; d++) outp[d] = acc[d] * inv;
    }
}

// ---------------- fused residual + LayerNorm: out = LN(A + Bsrc) -------------
__global__ void ln_kernel(const float* __restrict__ A,
                          const float* __restrict__ Bsrc,
                          const float* __restrict__ g,
                          const float* __restrict__ bta,
                          float* __restrict__ out)
{
    int row = blockIdx.x;
    int d = threadIdx.x;
    size_t off = (size_t)row*D + d;
    float v = A[off] + Bsrc[off];

    float s = v, s2 = v*v;
    #pragma unroll
    for (int o = 16; o > 0; o >>= 1) {
        s  += __shfl_xor_sync(0xffffffffu, s,  o);
        s2 += __shfl_xor_sync(0xffffffffu, s2, o);
    }
    __shared__ float ws[8], ws2[8];
    __shared__ float mu_s, rstd_s;
    int w = d >> 5;
    if ((d & 31) == 0) { ws[w] = s; ws2[w] = s2; }
    __syncthreads();
    if (d == 0) {
        float S1 = 0.f, S2 = 0.f;
        #pragma unroll
        for (int i = 0; i < 8; i++) { S1 += ws[i]; S2 += ws2[i]; }
        float mu = S1 * (1.f/256.f);
        float var = S2 * (1.f/256.f) - mu*mu;
        mu_s = mu;
        rstd_s = rsqrtf(var + 1e-5f);
    }
    __syncthreads();
    out[off] = (v - mu_s) * rstd_s * g[d] + bta[d];
}

// ---------------- final: LN cls row only + 2-layer head ----------------------
__global__ void head_kernel(const float* __restrict__ g,
                            const float* __restrict__ bta,
                            const float* __restrict__ Wh1,
                            const float* __restrict__ bh1,
                            const float* __restrict__ Wh2,
                            const float* __restrict__ bh2,
                            float* __restrict__ out)
{
    int b = blockIdx.x;
    int d = threadIdx.x;
    float v = g_x[(size_t)b*SLEN*D + d];

    float s = v, s2 = v*v;
    #pragma unroll
    for (int o = 16; o > 0; o >>= 1) {
        s  += __shfl_xor_sync(0xffffffffu, s,  o);
        s2 += __shfl_xor_sync(0xffffffffu, s2, o);
    }
    __shared__ float ws[8], ws2[8];
    __shared__ float mu_s, rstd_s;
    int w = d >> 5;
    if ((d & 31) == 0) { ws[w] = s; ws2[w] = s2; }
    __syncthreads();
    if (d == 0) {
        float S1 = 0.f, S2 = 0.f;
        #pragma unroll
        for (int i = 0; i < 8; i++) { S1 += ws[i]; S2 += ws2[i]; }
        float mu = S1 * (1.f/256.f);
        float var = S2 * (1.f/256.f) - mu*mu;
        mu_s = mu;
        rstd_s = rsqrtf(var + 1e-5f);
    }
    __syncthreads();

    __shared__ float clsr[256];
    __shared__ float hid[256];
    float c = (v - mu_s) * rstd_s * g[d] + bta[d];
    clsr[d] = c;
    out[b*D + d] = c;                       // cls_out
    __syncthreads();

    float hsum = bh1[d];
    #pragma unroll 8
    for (int k = 0; k < 256; k++) hsum = fmaf(clsr[k], Wh1[k*256 + d], hsum);
    hid[d] = fmaxf(hsum, 0.f);
    __syncthreads();

    if (d < 2) {
        float lg = bh2[d];
        for (int k = 0; k < 256; k++) lg = fmaf(hid[k], Wh2[k*2 + d], lg);
        out[BB*D + b*2 + d] = lg;           // logits after cls_out block
    }
}

// ---------------- launcher ---------------------------------------------------
extern "C" void kernel_launch(void* const* d_in, const int* in_sizes, int n_in,
                              void* d_out, int out_size)
{
    (void)in_sizes; (void)n_in; (void)out_size;

    const float* cf   = (const float*)d_in[0];
    const int*   xc   = (const int*)  d_in[1];
    const int*   yc   = (const int*)  d_in[2];
    const float* Wemb = (const float*)d_in[3];
    const float* bemb = (const float*)d_in[4];
    const float* Wct1 = (const float*)d_in[5];
    const float* bct1 = (const float*)d_in[6];
    const float* Wct2 = (const float*)d_in[7];
    const float* bct2 = (const float*)d_in[8];
    const float* cls  = (const float*)d_in[9];
    const float* Wq = (const float*)d_in[10]; const float* bq = (const float*)d_in[11];
    const float* Wk = (const float*)d_in[12]; const float* bk = (const float*)d_in[13];
    const float* Wv = (const float*)d_in[14]; const float* bv = (const float*)d_in[15];
    const float* Wo = (const float*)d_in[16]; const float* bo = (const float*)d_in[17];
    const float* ln1g = (const float*)d_in[18]; const float* ln1b = (const float*)d_in[19];
    const float* ln2g = (const float*)d_in[20]; const float* ln2b = (const float*)d_in[21];
    const float* Wf1 = (const float*)d_in[22]; const float* bf1 = (const float*)d_in[23];
    const float* Wf2 = (const float*)d_in[24]; const float* bf2 = (const float*)d_in[25];
    const float* lnfg = (const float*)d_in[26]; const float* lnfb = (const float*)d_in[27];
    const float* Wh1 = (const float*)d_in[28]; const float* bh1 = (const float*)d_in[29];
    const float* Wh2 = (const float*)d_in[30]; const float* bh2 = (const float*)d_in[31];
    float* out = (float*)d_out;

    void* p;
    cudaGetSymbolAddress(&p, g_x); float* xb = (float*)p;
    cudaGetSymbolAddress(&p, g_q); float* qb = (float*)p;
    cudaGetSymbolAddress(&p, g_k); float* kb = (float*)p;
    cudaGetSymbolAddress(&p, g_v); float* vb = (float*)p;
    cudaGetSymbolAddress(&p, g_a); float* ab = (float*)p;
    cudaGetSymbolAddress(&p, g_t); float* tb = (float*)p;
    cudaGetSymbolAddress(&p, g_h); float* hb = (float*)p;

    embed_kernel<<<MTOK, 256>>>(cf, xc, yc, Wemb, bemb, Wct1, bct1, Wct2, bct2, cls);

    dim3 g256((MTOK + 63)/64, D/64);
    dim3 gff ((MTOK + 63)/64, DFF/64);
    dim3 gattn((SLEN + 63)/64, NH, BB);

    for (int l = 0; l < NL; l++) {
        size_t wo = (size_t)l*D*D;
        gemm_kernel<<<g256, 256>>>(xb, Wq + wo, bq + l*D, qb, MTOK, D, D, 0);
        gemm_kernel<<<g256, 256>>>(xb, Wk + wo, bk + l*D, kb, MTOK, D, D, 0);
        gemm_kernel<<<g256, 256>>>(xb, Wv + wo, bv + l*D, vb, MTOK, D, D, 0);
        attn_kernel<<<gattn, 256>>>();
        gemm_kernel<<<g256, 256>>>(ab, Wo + wo, bo + l*D, tb, MTOK, D, D, 0);
        ln_kernel<<<MTOK, 256>>>(xb, tb, ln1g + l*D, ln1b + l*D, xb);
        gemm_kernel<<<gff, 256>>>(xb, Wf1 + (size_t)l*D*DFF, bf1 + l*DFF, hb, MTOK, DFF, D, 1);
        gemm_kernel<<<g256, 256>>>(hb, Wf2 + (size_t)l*DFF*D, bf2 + l*D, tb, MTOK, D, DFF, 0);
        ln_kernel<<<MTOK, 256>>>(xb, tb, ln2g + l*D, ln2b + l*D, xb);
    }

    head_kernel<<<BB, 256>>>(lnfg, lnfb, Wh1, bh1, Wh2, bh2, out);
}

// round 7
// speedup vs baseline: 2.1761x; 2.1761x over previous
#include <cuda_runtime.h>
#include <math.h>

#define BB   8
#define NCELL 1024
#define SLEN 1025
#define D    256
#define NH   8
#define HD   32
#define DFF  1024
#define NL   4
#define MTOK (BB*SLEN)   // 8200

// ---------------- scratch (static device globals; no allocs) ----------------
__device__ float g_x[MTOK*D];
__device__ float g_q[MTOK*D];
__device__ float g_k[MTOK*D];
__device__ float g_v[MTOK*D];
__device__ float g_a[MTOK*D];
__device__ float g_t[MTOK*D];
__device__ float g_h[(size_t)MTOK*DFF];

// ---------------- embedding: emb + cell-type MLP + positional + cls ----------
__global__ void embed_kernel(const float* __restrict__ cf,
                             const int* __restrict__ xc,
                             const int* __restrict__ yc,
                             const float* __restrict__ Wemb,
                             const float* __restrict__ bemb,
                             const float* __restrict__ Wct1,
                             const float* __restrict__ bct1,
                             const float* __restrict__ Wct2,
                             const float* __restrict__ bct2,
                             const float* __restrict__ cls)
{
    int blk = blockIdx.x;          // 0..8199
    int b = blk / SLEN;
    int s = blk % SLEN;
    int d = threadIdx.x;           // 0..255
    float* out = g_x + (size_t)blk * D;

    if (s == 0) { out[d] = cls[d]; return; }
    int n = s - 1;

    __shared__ float cfs[64];
    __shared__ float hs[128];
    const float* cfp = cf + ((size_t)b*NCELL + n)*64;
    if (d < 64) cfs[d] = cfp[d];
    __syncthreads();

    if (d < 128) {
        float acc = bct1[d];
        #pragma unroll
        for (int k = 0; k < 64; k++) acc = fmaf(cfs[k], Wct1[k*128 + d], acc);
        hs[d] = fmaxf(acc, 0.f);
    }
    __syncthreads();

    float e = bemb[d];
    #pragma unroll
    for (int k = 0; k < 64; k++) e = fmaf(cfs[k], Wemb[k*256 + d], e);
    float c2 = bct2[d];
    #pragma unroll
    for (int j = 0; j < 128; j++) c2 = fmaf(hs[j], Wct2[j*256 + d], c2);

    // positional encoding (match jax: div = exp(2m * (-ln(10000)/128)))
    int dd    = (d < 128) ? d : d - 128;
    int coord = (d < 128) ? xc[b*NCELL + n] : yc[b*NCELL + n];
    coord = min(max(coord, 0), 999);
    int m = dd >> 1;
    const float c1 = -0.07195578739046225f;  // float(-ln(10000)/128)
    float dv  = expf((float)(2*m) * c1);
    float ang = (float)coord * dv;
    float p   = (dd & 1) ? cosf(ang) : sinf(ang);

    out[d] = e + c2 + p;
}

// -------- tiled SGEMM: C = A(MxK) @ W(KxN) + bias [ReLU], BM=128 BN=64 BK=32 -
// 256 threads, 4x8 microtile (rows ar..ar+3; cols bc..bc+3 and bc+32..bc+35)
__global__ __launch_bounds__(256, 2)
void gemm_kernel(const float* __restrict__ A,
                 const float* __restrict__ W,
                 const float* __restrict__ bias,
                 float* __restrict__ C,
                 int M, int N, int K, int relu)
{
    __shared__ float As[32][132];   // [k][m] transposed, padded
    __shared__ float Bs[32][64];

    int tid = threadIdx.x;
    int m0 = blockIdx.x * 128;
    int n0 = blockIdx.y * 64;
    int ar = (tid >> 3) << 2;      // 0..124
    int bc = (tid & 7) << 2;       // 0..28

    float acc[4][8] = {};

    for (int k0 = 0; k0 < K; k0 += 32) {
        // A tile: 128 rows x 32 k -> 1024 float4, store transposed
        #pragma unroll
        for (int i = 0; i < 4; i++) {
            int idx = tid + i*256;
            int arow = idx >> 3;           // 0..127
            int kc   = (idx & 7) << 2;     // 0..28
            float4 va = make_float4(0.f,0.f,0.f,0.f);
            int gr = m0 + arow;
            if (gr < M) va = *(const float4*)(A + (size_t)gr*K + (k0 + kc));
            As[kc+0][arow] = va.x; As[kc+1][arow] = va.y;
            As[kc+2][arow] = va.z; As[kc+3][arow] = va.w;
        }
        // B tile: 32 k rows x 64 n -> 512 float4
        #pragma unroll
        for (int i = 0; i < 2; i++) {
            int idx = tid + i*256;
            int brow = idx >> 4;           // 0..31
            int bc4  = (idx & 15) << 2;    // 0..60
            *(float4*)&Bs[brow][bc4] =
                *(const float4*)(W + (size_t)(k0 + brow)*N + (n0 + bc4));
        }
        __syncthreads();

        #pragma unroll
        for (int kk = 0; kk < 32; kk++) {
            float a[4], bv[8];
            *(float4*)&a[0]  = *(float4*)&As[kk][ar];
            *(float4*)&bv[0] = *(float4*)&Bs[kk][bc];
            *(float4*)&bv[4] = *(float4*)&Bs[kk][bc + 32];
            #pragma unroll
            for (int r = 0; r < 4; r++) {
                #pragma unroll
                for (int c = 0; c < 8; c++)
                    acc[r][c] = fmaf(a[r], bv[c], acc[r][c]);
            }
        }
        __syncthreads();
    }

    float bb[8];
    *(float4*)&bb[0] = *(const float4*)(bias + n0 + bc);
    *(float4*)&bb[4] = *(const float4*)(bias + n0 + bc + 32);
    #pragma unroll
    for (int r = 0; r < 4; r++) {
        int gr = m0 + ar + r;
        if (gr < M) {
            float4 o0, o1;
            o0.x = acc[r][0] + bb[0]; o0.y = acc[r][1] + bb[1];
            o0.z = acc[r][2] + bb[2]; o0.w = acc[r][3] + bb[3];
            o1.x = acc[r][4] + bb[4]; o1.y = acc[r][5] + bb[5];
            o1.z = acc[r][6] + bb[6]; o1.w = acc[r][7] + bb[7];
            if (relu) {
                o0.x = fmaxf(o0.x, 0.f); o0.y = fmaxf(o0.y, 0.f);
                o0.z = fmaxf(o0.z, 0.f); o0.w = fmaxf(o0.w, 0.f);
                o1.x = fmaxf(o1.x, 0.f); o1.y = fmaxf(o1.y, 0.f);
                o1.z = fmaxf(o1.z, 0.f); o1.w = fmaxf(o1.w, 0.f);
            }
            float* cp = C + (size_t)gr*N + n0;
            *(float4*)(cp + bc)      = o0;
            *(float4*)(cp + bc + 32) = o1;
        }
    }
}

// ---------------- flash attention: q-tile 128, 2 rows/thread ------------------
// 256 threads: rl = tid>>2 owns rows (qt*128+rl) and (+64); sub = tid&3 owns
// k-columns {4j+sub} (interleaved -> conflict-free smem broadcast).
__global__ __launch_bounds__(256, 1) void attn_kernel()
{
    int qt = blockIdx.x;           // 0..8
    int h  = blockIdx.y;
    int b  = blockIdx.z;
    int tid = threadIdx.x;
    int rl  = tid >> 2;            // 0..63
    int sub = tid & 3;
    int q0r = qt*128 + rl;
    int q1r = q0r + 64;
    bool v0 = q0r < SLEN;
    bool v1 = q1r < SLEN;

    const float scale = 0.17677669529663687f;   // 1/sqrt(32)
    const float* qbase = g_q + (size_t)b*SLEN*D + h*HD;
    const float* kbase = g_k + (size_t)b*SLEN*D + h*HD;
    const float* vbase = g_v + (size_t)b*SLEN*D + h*HD;

    float q0[HD], q1[HD];
    #pragma unroll
    for (int d4 = 0; d4 < 8; d4++) {
        float4 t0 = make_float4(0.f,0.f,0.f,0.f);
        float4 t1 = make_float4(0.f,0.f,0.f,0.f);
        if (v0) t0 = *(const float4*)(qbase + (size_t)q0r*D + d4*4);
        if (v1) t1 = *(const float4*)(qbase + (size_t)q1r*D + d4*4);
        q0[d4*4+0] = t0.x*scale; q0[d4*4+1] = t0.y*scale;
        q0[d4*4+2] = t0.z*scale; q0[d4*4+3] = t0.w*scale;
        q1[d4*4+0] = t1.x*scale; q1[d4*4+1] = t1.y*scale;
        q1[d4*4+2] = t1.z*scale; q1[d4*4+3] = t1.w*scale;
    }

    __shared__ float ks[64][36];   // stride 36: 16B-aligned rows, banks spread
    __shared__ float vs[64][36];

    float m0 = -INFINITY, m1 = -INFINITY, l0 = 0.f, l1 = 0.f;
    float acc0[HD], acc1[HD];
    #pragma unroll
    for (int d = 0; d < HD; d++) { acc0[d] = 0.f; acc1[d] = 0.f; }

    const int ntiles = (SLEN + 63) / 64;   // 17
    for (int t = 0; t < ntiles; t++) {
        int k0 = t*64;
        __syncthreads();
        #pragma unroll
        for (int i = 0; i < 2; i++) {
            int idx = tid + i*256;         // 0..511 float4 slots
            int row = idx >> 3;
            int c4  = (idx & 7) << 2;
            float4 kv = make_float4(0.f,0.f,0.f,0.f);
            float4 vv = make_float4(0.f,0.f,0.f,0.f);
            int gk = k0 + row;
            if (gk < SLEN) {
                kv = *(const float4*)(kbase + (size_t)gk*D + c4);
                vv = *(const float4*)(vbase + (size_t)gk*D + c4);
            }
            *(float4*)&ks[row][c4] = kv;
            *(float4*)&vs[row][c4] = vv;
        }
        __syncthreads();

        float p0[16], p1[16];
        float t0 = -INFINITY, t1 = -INFINITY;
        #pragma unroll
        for (int j = 0; j < 16; j++) {
            int cl = 4*j + sub;            // interleaved column assignment
            float s0, s1;
            if (k0 + cl < SLEN) {
                s0 = 0.f; s1 = 0.f;
                #pragma unroll
                for (int d4 = 0; d4 < 8; d4++) {
                    float4 kv = *(const float4*)&ks[cl][d4*4];
                    s0 = fmaf(q0[d4*4+0], kv.x, s0);
                    s0 = fmaf(q0[d4*4+1], kv.y, s0);
                    s0 = fmaf(q0[d4*4+2], kv.z, s0);
                    s0 = fmaf(q0[d4*4+3], kv.w, s0);
                    s1 = fmaf(q1[d4*4+0], kv.x, s1);
                    s1 = fmaf(q1[d4*4+1], kv.y, s1);
                    s1 = fmaf(q1[d4*4+2], kv.z, s1);
                    s1 = fmaf(q1[d4*4+3], kv.w, s1);
                }
            } else { s0 = -INFINITY; s1 = -INFINITY; }
            p0[j] = s0; p1[j] = s1;
            t0 = fmaxf(t0, s0); t1 = fmaxf(t1, s1);
        }
        t0 = fmaxf(t0, __shfl_xor_sync(0xffffffffu, t0, 1));
        t0 = fmaxf(t0, __shfl_xor_sync(0xffffffffu, t0, 2));
        t1 = fmaxf(t1, __shfl_xor_sync(0xffffffffu, t1, 1));
        t1 = fmaxf(t1, __shfl_xor_sync(0xffffffffu, t1, 2));

        float mn0 = fmaxf(m0, t0), mn1 = fmaxf(m1, t1);
        float cr0 = __expf(m0 - mn0), cr1 = __expf(m1 - mn1);
        l0 *= cr0; l1 *= cr1;
        #pragma unroll
        for (int d = 0; d < HD; d++) { acc0[d] *= cr0; acc1[d] *= cr1; }

        float ls0 = 0.f, ls1 = 0.f;
        #pragma unroll
        for (int j = 0; j < 16; j++) {
            p0[j] = __expf(p0[j] - mn0); ls0 += p0[j];
            p1[j] = __expf(p1[j] - mn1); ls1 += p1[j];
        }
        l0 += ls0; l1 += ls1;

        #pragma unroll
        for (int j = 0; j < 16; j++) {
            int cl = 4*j + sub;
            float pj0 = p0[j], pj1 = p1[j];
            #pragma unroll
            for (int d4 = 0; d4 < 8; d4++) {
                float4 vv = *(const float4*)&vs[cl][d4*4];
                acc0[d4*4+0] = fmaf(pj0, vv.x, acc0[d4*4+0]);
                acc0[d4*4+1] = fmaf(pj0, vv.y, acc0[d4*4+1]);
                acc0[d4*4+2] = fmaf(pj0, vv.z, acc0[d4*4+2]);
                acc0[d4*4+3] = fmaf(pj0, vv.w, acc0[d4*4+3]);
                acc1[d4*4+0] = fmaf(pj1, vv.x, acc1[d4*4+0]);
                acc1[d4*4+1] = fmaf(pj1, vv.y, acc1[d4*4+1]);
                acc1[d4*4+2] = fmaf(pj1, vv.z, acc1[d4*4+2]);
                acc1[d4*4+3] = fmaf(pj1, vv.w, acc1[d4*4+3]);
            }
        }
        m0 = mn0; m1 = mn1;
    }

    // reduce across the 4 sub-threads of each row
    l0 += __shfl_xor_sync(0xffffffffu, l0, 1);
    l0 += __shfl_xor_sync(0xffffffffu, l0, 2);
    l1 += __shfl_xor_sync(0xffffffffu, l1, 1);
    l1 += __shfl_xor_sync(0xffffffffu, l1, 2);
    #pragma unroll
    for (int d = 0; d < HD; d++) {
        acc0[d] += __shfl_xor_sync(0xffffffffu, acc0[d], 1);
        acc0[d] += __shfl_xor_sync(0xffffffffu, acc0[d], 2);
        acc1[d] += __shfl_xor_sync(0xffffffffu, acc1[d], 1);
        acc1[d] += __shfl_xor_sync(0xffffffffu, acc1[d], 2);
    }

    if (sub == 0) {
        if (v0) {
            float inv = 1.f / l0;
            float* op = g_a + ((size_t)b*SLEN + q0r)*D + h*HD;
            #pragma unroll
            for (int d4 = 0; d4 < 8; d4++) {
                float4 o;
                o.x = acc0[d4*4+0]*inv; o.y = acc0[d4*4+1]*inv;
                o.z = acc0[d4*4+2]*inv; o.w = acc0[d4*4+3]*inv;
                *(float4*)(op + d4*4) = o;
            }
        }
        if (v1) {
            float inv = 1.f / l1;
            float* op = g_a + ((size_t)b*SLEN + q1r)*D + h*HD;
            #pragma unroll
            for (int d4 = 0; d4 < 8; d4++) {
                float4 o;
                o.x = acc1[d4*4+0]*inv; o.y = acc1[d4*4+1]*inv;
                o.z = acc1[d4*4+2]*inv; o.w = acc1[d4*4+3]*inv;
                *(float4*)(op + d4*4) = o;
            }
        }
    }
}

// ---------------- fused residual + LayerNorm: out = LN(A + Bsrc) -------------
__global__ void ln_kernel(const float* __restrict__ A,
                          const float* __restrict__ Bsrc,
                          const float* __restrict__ g,
                          const float* __restrict__ bta,
                          float* __restrict__ out)
{
    int row = blockIdx.x;
    int d = threadIdx.x;
    size_t off = (size_t)row*D + d;
    float v = A[off] + Bsrc[off];

    float s = v, s2 = v*v;
    #pragma unroll
    for (int o = 16; o > 0; o >>= 1) {
        s  += __shfl_xor_sync(0xffffffffu, s,  o);
        s2 += __shfl_xor_sync(0xffffffffu, s2, o);
    }
    __shared__ float ws[8], ws2[8];
    __shared__ float mu_s, rstd_s;
    int w = d >> 5;
    if ((d & 31) == 0) { ws[w] = s; ws2[w] = s2; }
    __syncthreads();
    if (d == 0) {
        float S1 = 0.f, S2 = 0.f;
        #pragma unroll
        for (int i = 0; i < 8; i++) { S1 += ws[i]; S2 += ws2[i]; }
        float mu = S1 * (1.f/256.f);
        float var = S2 * (1.f/256.f) - mu*mu;
        mu_s = mu;
        rstd_s = rsqrtf(var + 1e-5f);
    }
    __syncthreads();
    out[off] = (v - mu_s) * rstd_s * g[d] + bta[d];
}

// ---------------- final: LN cls row only + 2-layer head ----------------------
__global__ void head_kernel(const float* __restrict__ g,
                            const float* __restrict__ bta,
                            const float* __restrict__ Wh1,
                            const float* __restrict__ bh1,
                            const float* __restrict__ Wh2,
                            const float* __restrict__ bh2,
                            float* __restrict__ out)
{
    int b = blockIdx.x;
    int d = threadIdx.x;
    float v = g_x[(size_t)b*SLEN*D + d];

    float s = v, s2 = v*v;
    #pragma unroll
    for (int o = 16; o > 0; o >>= 1) {
        s  += __shfl_xor_sync(0xffffffffu, s,  o);
        s2 += __shfl_xor_sync(0xffffffffu, s2, o);
    }
    __shared__ float ws[8], ws2[8];
    __shared__ float mu_s, rstd_s;
    int w = d >> 5;
    if ((d & 31) == 0) { ws[w] = s; ws2[w] = s2; }
    __syncthreads();
    if (d == 0) {
        float S1 = 0.f, S2 = 0.f;
        #pragma unroll
        for (int i = 0; i < 8; i++) { S1 += ws[i]; S2 += ws2[i]; }
        float mu = S1 * (1.f/256.f);
        float var = S2 * (1.f/256.f) - mu*mu;
        mu_s = mu;
        rstd_s = rsqrtf(var + 1e-5f);
    }
    __syncthreads();

    __shared__ float clsr[256];
    __shared__ float hid[256];
    float c = (v - mu_s) * rstd_s * g[d] + bta[d];
    clsr[d] = c;
    out[b*D + d] = c;                       // cls_out
    __syncthreads();

    float hsum = bh1[d];
    #pragma unroll 8
    for (int k = 0; k < 256; k++) hsum = fmaf(clsr[k], Wh1[k*256 + d], hsum);
    hid[d] = fmaxf(hsum, 0.f);
    __syncthreads();

    if (d < 2) {
        float lg = bh2[d];
        for (int k = 0; k < 256; k++) lg = fmaf(hid[k], Wh2[k*2 + d], lg);
        out[BB*D + b*2 + d] = lg;           // logits after cls_out block
    }
}

// ---------------- launcher ---------------------------------------------------
extern "C" void kernel_launch(void* const* d_in, const int* in_sizes, int n_in,
                              void* d_out, int out_size)
{
    (void)in_sizes; (void)n_in; (void)out_size;

    const float* cf   = (const float*)d_in[0];
    const int*   xc   = (const int*)  d_in[1];
    const int*   yc   = (const int*)  d_in[2];
    const float* Wemb = (const float*)d_in[3];
    const float* bemb = (const float*)d_in[4];
    const float* Wct1 = (const float*)d_in[5];
    const float* bct1 = (const float*)d_in[6];
    const float* Wct2 = (const float*)d_in[7];
    const float* bct2 = (const float*)d_in[8];
    const float* cls  = (const float*)d_in[9];
    const float* Wq = (const float*)d_in[10]; const float* bq = (const float*)d_in[11];
    const float* Wk = (const float*)d_in[12]; const float* bk = (const float*)d_in[13];
    const float* Wv = (const float*)d_in[14]; const float* bv = (const float*)d_in[15];
    const float* Wo = (const float*)d_in[16]; const float* bo = (const float*)d_in[17];
    const float* ln1g = (const float*)d_in[18]; const float* ln1b = (const float*)d_in[19];
    const float* ln2g = (const float*)d_in[20]; const float* ln2b = (const float*)d_in[21];
    const float* Wf1 = (const float*)d_in[22]; const float* bf1 = (const float*)d_in[23];
    const float* Wf2 = (const float*)d_in[24]; const float* bf2 = (const float*)d_in[25];
    const float* lnfg = (const float*)d_in[26]; const float* lnfb = (const float*)d_in[27];
    const float* Wh1 = (const float*)d_in[28]; const float* bh1 = (const float*)d_in[29];
    const float* Wh2 = (const float*)d_in[30]; const float* bh2 = (const float*)d_in[31];
    float* out = (float*)d_out;

    void* p;
    cudaGetSymbolAddress(&p, g_x); float* xb = (float*)p;
    cudaGetSymbolAddress(&p, g_q); float* qb = (float*)p;
    cudaGetSymbolAddress(&p, g_k); float* kb = (float*)p;
    cudaGetSymbolAddress(&p, g_v); float* vb = (float*)p;
    cudaGetSymbolAddress(&p, g_a); float* ab = (float*)p;
    cudaGetSymbolAddress(&p, g_t); float* tb = (float*)p;
    cudaGetSymbolAddress(&p, g_h); float* hb = (float*)p;

    embed_kernel<<<MTOK, 256>>>(cf, xc, yc, Wemb, bemb, Wct1, bct1, Wct2, bct2, cls);

    dim3 g256((MTOK + 127)/128, D/64);     // 65 x 4
    dim3 gff ((MTOK + 127)/128, DFF/64);   // 65 x 16
    dim3 gattn((SLEN + 127)/128, NH, BB);  // 9 x 8 x 8

    for (int l = 0; l < NL; l++) {
        size_t wo = (size_t)l*D*D;
        gemm_kernel<<<g256, 256>>>(xb, Wq + wo, bq + l*D, qb, MTOK, D, D, 0);
        gemm_kernel<<<g256, 256>>>(xb, Wk + wo, bk + l*D, kb, MTOK, D, D, 0);
        gemm_kernel<<<g256, 256>>>(xb, Wv + wo, bv + l*D, vb, MTOK, D, D, 0);
        attn_kernel<<<gattn, 256>>>();
        gemm_kernel<<<g256, 256>>>(ab, Wo + wo, bo + l*D, tb, MTOK, D, D, 0);
        ln_kernel<<<MTOK, 256>>>(xb, tb, ln1g + l*D, ln1b + l*D, xb);
        gemm_kernel<<<gff, 256>>>(xb, Wf1 + (size_t)l*D*DFF, bf1 + l*DFF, hb, MTOK, DFF, D, 1);
        gemm_kernel<<<g256, 256>>>(hb, Wf2 + (size_t)l*DFF*D, bf2 + l*D, tb, MTOK, D, DFF, 0);
        ln_kernel<<<MTOK, 256>>>(xb, tb, ln2g + l*D, ln2b + l*D, xb);
    }

    head_kernel<<<BB, 256>>>(lnfg, lnfb, Wh1, bh1, Wh2, bh2, out);
}

// round 8
// speedup vs baseline: 2.3014x; 1.0576x over previous
#include <cuda_runtime.h>
#include <math.h>
#include <stdint.h>

#define BB   8
#define NCELL 1024
#define SLEN 1025
#define D    256
#define NH   8
#define HD   32
#define DFF  1024
#define NL   4
#define MTOK (BB*SLEN)   // 8200

// ---------------- scratch (static device globals; no allocs) ----------------
__device__ float g_x[MTOK*D];
__device__ float g_q[MTOK*D];
__device__ float g_k[MTOK*D];
__device__ float g_v[MTOK*D];
__device__ float g_a[MTOK*D];
__device__ float g_t[MTOK*D];
__device__ float g_h[(size_t)MTOK*DFF];

// cp.async helper: 16B global->shared, zero-fill when sz==0
#define CPA16(dst, src, sz) \
    asm volatile("cp.async.cg.shared.global [%0], [%1], 16, %2;" \
        :: "r"((uint32_t)__cvta_generic_to_shared(dst)), "l"(src), "r"(sz))

// ---------------- embedding: emb + cell-type MLP + positional + cls ----------
__global__ void embed_kernel(const float* __restrict__ cf,
                             const int* __restrict__ xc,
                             const int* __restrict__ yc,
                             const float* __restrict__ Wemb,
                             const float* __restrict__ bemb,
                             const float* __restrict__ Wct1,
                             const float* __restrict__ bct1,
                             const float* __restrict__ Wct2,
                             const float* __restrict__ bct2,
                             const float* __restrict__ cls)
{
    int blk = blockIdx.x;          // 0..8199
    int b = blk / SLEN;
    int s = blk % SLEN;
    int d = threadIdx.x;           // 0..255
    float* out = g_x + (size_t)blk * D;

    if (s == 0) { out[d] = cls[d]; return; }
    int n = s - 1;

    __shared__ float cfs[64];
    __shared__ float hs[128];
    const float* cfp = cf + ((size_t)b*NCELL + n)*64;
    if (d < 64) cfs[d] = cfp[d];
    __syncthreads();

    if (d < 128) {
        float acc = bct1[d];
        #pragma unroll
        for (int k = 0; k < 64; k++) acc = fmaf(cfs[k], Wct1[k*128 + d], acc);
        hs[d] = fmaxf(acc, 0.f);
    }
    __syncthreads();

    float e = bemb[d];
    #pragma unroll
    for (int k = 0; k < 64; k++) e = fmaf(cfs[k], Wemb[k*256 + d], e);
    float c2 = bct2[d];
    #pragma unroll
    for (int j = 0; j < 128; j++) c2 = fmaf(hs[j], Wct2[j*256 + d], c2);

    // positional encoding (match jax: div = exp(2m * (-ln(10000)/128)))
    int dd    = (d < 128) ? d : d - 128;
    int coord = (d < 128) ? xc[b*NCELL + n] : yc[b*NCELL + n];
    coord = min(max(coord, 0), 999);
    int m = dd >> 1;
    const float c1 = -0.07195578739046225f;  // float(-ln(10000)/128)
    float dv  = expf((float)(2*m) * c1);
    float ang = (float)coord * dv;
    float p   = (dd & 1) ? cosf(ang) : sinf(ang);

    out[d] = e + c2 + p;
}

// ---- SGEMM: C = A(MxK) @ W(KxN) + bias [ReLU]; BM=128 BN=128 BK=16 ----------
// 256 threads, 8x8 microtile, double-buffered smem, register prefetch.
__global__ __launch_bounds__(256, 2)
void gemm_kernel(const float* __restrict__ A,
                 const float* __restrict__ W,
                 const float* __restrict__ bias,
                 float* __restrict__ C,
                 int M, int N, int K, int relu)
{
    __shared__ float As[2][16][132];   // [buf][k][m] transposed, padded
    __shared__ float Bs[2][16][128];   // [buf][k][n]

    int tid = threadIdx.x;
    int m0 = blockIdx.x * 128;
    int n0 = blockIdx.y * 128;
    int ar = (tid >> 4) << 3;      // 0..120
    int bc = (tid & 15) << 3;      // 0..120

    // load mapping: A float4 f=tid -> row f>>2, kc (f&3)*4 ; f=tid+256 -> row+64
    int arow = tid >> 2;           // 0..63
    int akc  = (tid & 3) << 2;
    // B float4 f=tid -> krow f>>5, nc (f&31)*4 ; f=tid+256 -> krow+8
    int bkr = tid >> 5;            // 0..7
    int bnc = (tid & 31) << 2;

    bool av0 = (m0 + arow)      < M;
    bool av1 = (m0 + arow + 64) < M;
    const float* Ap0 = A + (size_t)(m0 + arow)      * K + akc;
    const float* Ap1 = A + (size_t)(m0 + arow + 64) * K + akc;
    const float* Bp0 = W + (size_t)bkr       * N + n0 + bnc;
    const float* Bp1 = W + (size_t)(bkr + 8) * N + n0 + bnc;

    float acc[8][8] = {};

    // prologue: tile 0 -> buffer 0
    {
        float4 a0 = av0 ? *(const float4*)Ap0 : make_float4(0.f,0.f,0.f,0.f);
        float4 a1 = av1 ? *(const float4*)Ap1 : make_float4(0.f,0.f,0.f,0.f);
        float4 b0 = *(const float4*)Bp0;
        float4 b1 = *(const float4*)Bp1;
        As[0][akc+0][arow] = a0.x; As[0][akc+1][arow] = a0.y;
        As[0][akc+2][arow] = a0.z; As[0][akc+3][arow] = a0.w;
        As[0][akc+0][arow+64] = a1.x; As[0][akc+1][arow+64] = a1.y;
        As[0][akc+2][arow+64] = a1.z; As[0][akc+3][arow+64] = a1.w;
        *(float4*)&Bs[0][bkr  ][bnc] = b0;
        *(float4*)&Bs[0][bkr+8][bnc] = b1;
    }
    __syncthreads();

    int KT = K >> 4;
    for (int kt = 0; kt < KT; kt++) {
        int cur = kt & 1;
        float4 pa0, pa1, pb0, pb1;
        bool more = (kt + 1 < KT);
        if (more) {
            int k0 = (kt + 1) << 4;
            pa0 = av0 ? *(const float4*)(Ap0 + k0) : make_float4(0.f,0.f,0.f,0.f);
            pa1 = av1 ? *(const float4*)(Ap1 + k0) : make_float4(0.f,0.f,0.f,0.f);
            pb0 = *(const float4*)(Bp0 + (size_t)k0 * N);
            pb1 = *(const float4*)(Bp1 + (size_t)k0 * N);
        }

        #pragma unroll
        for (int kk = 0; kk < 16; kk++) {
            float a[8], b[8];
            *(float4*)&a[0] = *(float4*)&As[cur][kk][ar];
            *(float4*)&a[4] = *(float4*)&As[cur][kk][ar+4];
            *(float4*)&b[0] = *(float4*)&Bs[cur][kk][bc];
            *(float4*)&b[4] = *(float4*)&Bs[cur][kk][bc+4];
            #pragma unroll
            for (int r = 0; r < 8; r++) {
                #pragma unroll
                for (int c = 0; c < 8; c++)
                    acc[r][c] = fmaf(a[r], b[c], acc[r][c]);
            }
        }

        if (more) {
            int nxt = cur ^ 1;
            As[nxt][akc+0][arow] = pa0.x; As[nxt][akc+1][arow] = pa0.y;
            As[nxt][akc+2][arow] = pa0.z; As[nxt][akc+3][arow] = pa0.w;
            As[nxt][akc+0][arow+64] = pa1.x; As[nxt][akc+1][arow+64] = pa1.y;
            As[nxt][akc+2][arow+64] = pa1.z; As[nxt][akc+3][arow+64] = pa1.w;
            *(float4*)&Bs[nxt][bkr  ][bnc] = pb0;
            *(float4*)&Bs[nxt][bkr+8][bnc] = pb1;
            __syncthreads();
        }
    }

    float bb[8];
    *(float4*)&bb[0] = *(const float4*)(bias + n0 + bc);
    *(float4*)&bb[4] = *(const float4*)(bias + n0 + bc + 4);
    #pragma unroll
    for (int r = 0; r < 8; r++) {
        int gr = m0 + ar + r;
        if (gr < M) {
            float4 o0, o1;
            o0.x = acc[r][0] + bb[0]; o0.y = acc[r][1] + bb[1];
            o0.z = acc[r][2] + bb[2]; o0.w = acc[r][3] + bb[3];
            o1.x = acc[r][4] + bb[4]; o1.y = acc[r][5] + bb[5];
            o1.z = acc[r][6] + bb[6]; o1.w = acc[r][7] + bb[7];
            if (relu) {
                o0.x = fmaxf(o0.x, 0.f); o0.y = fmaxf(o0.y, 0.f);
                o0.z = fmaxf(o0.z, 0.f); o0.w = fmaxf(o0.w, 0.f);
                o1.x = fmaxf(o1.x, 0.f); o1.y = fmaxf(o1.y, 0.f);
                o1.z = fmaxf(o1.z, 0.f); o1.w = fmaxf(o1.w, 0.f);
            }
            float* cp = C + (size_t)gr*N + n0 + bc;
            *(float4*)(cp)     = o0;
            *(float4*)(cp + 4) = o1;
        }
    }
}

// ---------------- flash attention: q-tile 128, cp.async double buffering -----
__shared__ float attn_smem_dummy[1]; // (unused, keeps nvcc happy about layout)

__device__ __forceinline__ void attn_issue_tile(
    const float* kbase, const float* vbase,
    float (*ks)[64][36], float (*vs)[64][36],
    int buf, int t, int row0, int c4)
{
    int k0  = t * 64;
    int gk0 = k0 + row0;
    int gk1 = gk0 + 32;
    int s0 = (gk0 < SLEN) ? 16 : 0;
    int s1 = (gk1 < SLEN) ? 16 : 0;
    int ck0 = min(gk0, SLEN-1);
    int ck1 = min(gk1, SLEN-1);
    CPA16(&ks[buf][row0   ][c4], kbase + (size_t)ck0*D + c4, s0);
    CPA16(&ks[buf][row0+32][c4], kbase + (size_t)ck1*D + c4, s1);
    CPA16(&vs[buf][row0   ][c4], vbase + (size_t)ck0*D + c4, s0);
    CPA16(&vs[buf][row0+32][c4], vbase + (size_t)ck1*D + c4, s1);
    asm volatile("cp.async.commit_group;");
}

__global__ void attn_kernel()
{
    __shared__ float ks[2][64][36];
    __shared__ float vs[2][64][36];

    int qt = blockIdx.x;           // 0..8
    int h  = blockIdx.y;
    int b  = blockIdx.z;
    int tid = threadIdx.x;
    int rl  = tid >> 2;            // 0..63
    int sub = tid & 3;
    int q0r = qt*128 + rl;
    int q1r = q0r + 64;
    bool v0 = q0r < SLEN;
    bool v1 = q1r < SLEN;

    int row0 = tid >> 3;           // 0..31 (load mapping)
    int c4   = (tid & 7) << 2;

    const float scale = 0.17677669529663687f;   // 1/sqrt(32)
    const float* qbase = g_q + (size_t)b*SLEN*D + h*HD;
    const float* kbase = g_k + (size_t)b*SLEN*D + h*HD;
    const float* vbase = g_v + (size_t)b*SLEN*D + h*HD;

    float q0[HD], q1[HD];
    #pragma unroll
    for (int d4 = 0; d4 < 8; d4++) {
        float4 t0 = make_float4(0.f,0.f,0.f,0.f);
        float4 t1 = make_float4(0.f,0.f,0.f,0.f);
        if (v0) t0 = *(const float4*)(qbase + (size_t)q0r*D + d4*4);
        if (v1) t1 = *(const float4*)(qbase + (size_t)q1r*D + d4*4);
        q0[d4*4+0] = t0.x*scale; q0[d4*4+1] = t0.y*scale;
        q0[d4*4+2] = t0.z*scale; q0[d4*4+3] = t0.w*scale;
        q1[d4*4+0] = t1.x*scale; q1[d4*4+1] = t1.y*scale;
        q1[d4*4+2] = t1.z*scale; q1[d4*4+3] = t1.w*scale;
    }

    float m0 = -INFINITY, m1 = -INFINITY, l0 = 0.f, l1 = 0.f;
    float acc0[HD], acc1[HD];
    #pragma unroll
    for (int d = 0; d < HD; d++) { acc0[d] = 0.f; acc1[d] = 0.f; }

    const int ntiles = (SLEN + 63) / 64;   // 17

    attn_issue_tile(kbase, vbase, ks, vs, 0, 0, row0, c4);

    for (int t = 0; t < ntiles; t++) {
        int cur = t & 1;
        int k0 = t*64;
        if (t + 1 < ntiles) {
            attn_issue_tile(kbase, vbase, ks, vs, cur ^ 1, t + 1, row0, c4);
            asm volatile("cp.async.wait_group 1;");
        } else {
            asm volatile("cp.async.wait_group 0;");
        }
        __syncthreads();

        float p0[16], p1[16];
        float t0 = -INFINITY, t1 = -INFINITY;
        #pragma unroll
        for (int j = 0; j < 16; j++) {
            int cl = 4*j + sub;            // interleaved column assignment
            float s0, s1;
            if (k0 + cl < SLEN) {
                s0 = 0.f; s1 = 0.f;
                #pragma unroll
                for (int d4 = 0; d4 < 8; d4++) {
                    float4 kv = *(const float4*)&ks[cur][cl][d4*4];
                    s0 = fmaf(q0[d4*4+0], kv.x, s0);
                    s0 = fmaf(q0[d4*4+1], kv.y, s0);
                    s0 = fmaf(q0[d4*4+2], kv.z, s0);
                    s0 = fmaf(q0[d4*4+3], kv.w, s0);
                    s1 = fmaf(q1[d4*4+0], kv.x, s1);
                    s1 = fmaf(q1[d4*4+1], kv.y, s1);
                    s1 = fmaf(q1[d4*4+2], kv.z, s1);
                    s1 = fmaf(q1[d4*4+3], kv.w, s1);
                }
            } else { s0 = -INFINITY; s1 = -INFINITY; }
            p0[j] = s0; p1[j] = s1;
            t0 = fmaxf(t0, s0); t1 = fmaxf(t1, s1);
        }
        t0 = fmaxf(t0, __shfl_xor_sync(0xffffffffu, t0, 1));
        t0 = fmaxf(t0, __shfl_xor_sync(0xffffffffu, t0, 2));
        t1 = fmaxf(t1, __shfl_xor_sync(0xffffffffu, t1, 1));
        t1 = fmaxf(t1, __shfl_xor_sync(0xffffffffu, t1, 2));

        float mn0 = fmaxf(m0, t0), mn1 = fmaxf(m1, t1);
        float cr0 = __expf(m0 - mn0), cr1 = __expf(m1 - mn1);
        l0 *= cr0; l1 *= cr1;
        #pragma unroll
        for (int d = 0; d < HD; d++) { acc0[d] *= cr0; acc1[d] *= cr1; }

        float ls0 = 0.f, ls1 = 0.f;
        #pragma unroll
        for (int j = 0; j < 16; j++) {
            p0[j] = __expf(p0[j] - mn0); ls0 += p0[j];
            p1[j] = __expf(p1[j] - mn1); ls1 += p1[j];
        }
        l0 += ls0; l1 += ls1;

        #pragma unroll
        for (int j = 0; j < 16; j++) {
            int cl = 4*j + sub;
            float pj0 = p0[j], pj1 = p1[j];
            #pragma unroll
            for (int d4 = 0; d4 < 8; d4++) {
                float4 vv = *(const float4*)&vs[cur][cl][d4*4];
                acc0[d4*4+0] = fmaf(pj0, vv.x, acc0[d4*4+0]);
                acc0[d4*4+1] = fmaf(pj0, vv.y, acc0[d4*4+1]);
                acc0[d4*4+2] = fmaf(pj0, vv.z, acc0[d4*4+2]);
                acc0[d4*4+3] = fmaf(pj0, vv.w, acc0[d4*4+3]);
                acc1[d4*4+0] = fmaf(pj1, vv.x, acc1[d4*4+0]);
                acc1[d4*4+1] = fmaf(pj1, vv.y, acc1[d4*4+1]);
                acc1[d4*4+2] = fmaf(pj1, vv.z, acc1[d4*4+2]);
                acc1[d4*4+3] = fmaf(pj1, vv.w, acc1[d4*4+3]);
            }
        }
        m0 = mn0; m1 = mn1;
        __syncthreads();   // protect buffer before t+1 overwrites cur^1's sibling
    }

    // reduce across the 4 sub-threads of each row
    l0 += __shfl_xor_sync(0xffffffffu, l0, 1);
    l0 += __shfl_xor_sync(0xffffffffu, l0, 2);
    l1 += __shfl_xor_sync(0xffffffffu, l1, 1);
    l1 += __shfl_xor_sync(0xffffffffu, l1, 2);
    #pragma unroll
    for (int d = 0; d < HD; d++) {
        acc0[d] += __shfl_xor_sync(0xffffffffu, acc0[d], 1);
        acc0[d] += __shfl_xor_sync(0xffffffffu, acc0[d], 2);
        acc1[d] += __shfl_xor_sync(0xffffffffu, acc1[d], 1);
        acc1[d] += __shfl_xor_sync(0xffffffffu, acc1[d], 2);
    }

    if (sub == 0) {
        if (v0) {
            float inv = 1.f / l0;
            float* op = g_a + ((size_t)b*SLEN + q0r)*D + h*HD;
            #pragma unroll
            for (int d4 = 0; d4 < 8; d4++) {
                float4 o;
                o.x = acc0[d4*4+0]*inv; o.y = acc0[d4*4+1]*inv;
                o.z = acc0[d4*4+2]*inv; o.w = acc0[d4*4+3]*inv;
                *(float4*)(op + d4*4) = o;
            }
        }
        if (v1) {
            float inv = 1.f / l1;
            float* op = g_a + ((size_t)b*SLEN + q1r)*D + h*HD;
            #pragma unroll
            for (int d4 = 0; d4 < 8; d4++) {
                float4 o;
                o.x = acc1[d4*4+0]*inv; o.y = acc1[d4*4+1]*inv;
                o.z = acc1[d4*4+2]*inv; o.w = acc1[d4*4+3]*inv;
                *(float4*)(op + d4*4) = o;
            }
        }
    }
}

// ---------- fused residual + LayerNorm, warp-per-row (8 rows/block) ----------
__global__ void ln_kernel(const float* __restrict__ A,
                          const float* __restrict__ Bsrc,
                          const float* __restrict__ g,
                          const float* __restrict__ bta,
                          float* __restrict__ out)
{
    int warp = threadIdx.x >> 5;
    int lane = threadIdx.x & 31;
    int row = blockIdx.x * 8 + warp;
    size_t base = (size_t)row * D;

    const float4* ap = (const float4*)(A + base);
    const float4* bp = (const float4*)(Bsrc + base);
    float4 a0 = ap[lane], a1 = ap[lane + 32];
    float4 b0 = bp[lane], b1 = bp[lane + 32];
    float v[8];
    v[0]=a0.x+b0.x; v[1]=a0.y+b0.y; v[2]=a0.z+b0.z; v[3]=a0.w+b0.w;
    v[4]=a1.x+b1.x; v[5]=a1.y+b1.y; v[6]=a1.z+b1.z; v[7]=a1.w+b1.w;

    float s = 0.f, s2 = 0.f;
    #pragma unroll
    for (int i = 0; i < 8; i++) { s += v[i]; s2 = fmaf(v[i], v[i], s2); }
    #pragma unroll
    for (int o = 16; o > 0; o >>= 1) {
        s  += __shfl_xor_sync(0xffffffffu, s,  o);
        s2 += __shfl_xor_sync(0xffffffffu, s2, o);
    }
    float mu = s * (1.f/256.f);
    float var = s2 * (1.f/256.f) - mu*mu;
    float rstd = rsqrtf(var + 1e-5f);

    const float4* gp = (const float4*)g;
    const float4* tp = (const float4*)bta;
    float4 g0 = gp[lane], g1 = gp[lane+32];
    float4 t0 = tp[lane], t1 = tp[lane+32];
    float4 o0, o1;
    o0.x = (v[0]-mu)*rstd*g0.x + t0.x;
    o0.y = (v[1]-mu)*rstd*g0.y + t0.y;
    o0.z = (v[2]-mu)*rstd*g0.z + t0.z;
    o0.w = (v[3]-mu)*rstd*g0.w + t0.w;
    o1.x = (v[4]-mu)*rstd*g1.x + t1.x;
    o1.y = (v[5]-mu)*rstd*g1.y + t1.y;
    o1.z = (v[6]-mu)*rstd*g1.z + t1.z;
    o1.w = (v[7]-mu)*rstd*g1.w + t1.w;
    float4* op = (float4*)(out + base);
    op[lane]      = o0;
    op[lane + 32] = o1;
}

// ---------------- final: LN cls row only + 2-layer head ----------------------
__global__ void head_kernel(const float* __restrict__ g,
                            const float* __restrict__ bta,
                            const float* __restrict__ Wh1,
                            const float* __restrict__ bh1,
                            const float* __restrict__ Wh2,
                            const float* __restrict__ bh2,
                            float* __restrict__ out)
{
    int b = blockIdx.x;
    int d = threadIdx.x;
    float v = g_x[(size_t)b*SLEN*D + d];

    float s = v, s2 = v*v;
    #pragma unroll
    for (int o = 16; o > 0; o >>= 1) {
        s  += __shfl_xor_sync(0xffffffffu, s,  o);
        s2 += __shfl_xor_sync(0xffffffffu, s2, o);
    }
    __shared__ float ws[8], ws2[8];
    __shared__ float mu_s, rstd_s;
    int w = d >> 5;
    if ((d & 31) == 0) { ws[w] = s; ws2[w] = s2; }
    __syncthreads();
    if (d == 0) {
        float S1 = 0.f, S2 = 0.f;
        #pragma unroll
        for (int i = 0; i < 8; i++) { S1 += ws[i]; S2 += ws2[i]; }
        float mu = S1 * (1.f/256.f);
        float var = S2 * (1.f/256.f) - mu*mu;
        mu_s = mu;
        rstd_s = rsqrtf(var + 1e-5f);
    }
    __syncthreads();

    __shared__ float clsr[256];
    __shared__ float hid[256];
    float c = (v - mu_s) * rstd_s * g[d] + bta[d];
    clsr[d] = c;
    out[b*D + d] = c;                       // cls_out
    __syncthreads();

    float hsum = bh1[d];
    #pragma unroll 8
    for (int k = 0; k < 256; k++) hsum = fmaf(clsr[k], Wh1[k*256 + d], hsum);
    hid[d] = fmaxf(hsum, 0.f);
    __syncthreads();

    if (d < 2) {
        float lg = bh2[d];
        for (int k = 0; k < 256; k++) lg = fmaf(hid[k], Wh2[k*2 + d], lg);
        out[BB*D + b*2 + d] = lg;           // logits after cls_out block
    }
}

// ---------------- launcher ---------------------------------------------------
extern "C" void kernel_launch(void* const* d_in, const int* in_sizes, int n_in,
                              void* d_out, int out_size)
{
    (void)in_sizes; (void)n_in; (void)out_size;

    const float* cf   = (const float*)d_in[0];
    const int*   xc   = (const int*)  d_in[1];
    const int*   yc   = (const int*)  d_in[2];
    const float* Wemb = (const float*)d_in[3];
    const float* bemb = (const float*)d_in[4];
    const float* Wct1 = (const float*)d_in[5];
    const float* bct1 = (const float*)d_in[6];
    const float* Wct2 = (const float*)d_in[7];
    const float* bct2 = (const float*)d_in[8];
    const float* cls  = (const float*)d_in[9];
    const float* Wq = (const float*)d_in[10]; const float* bq = (const float*)d_in[11];
    const float* Wk = (const float*)d_in[12]; const float* bk = (const float*)d_in[13];
    const float* Wv = (const float*)d_in[14]; const float* bv = (const float*)d_in[15];
    const float* Wo = (const float*)d_in[16]; const float* bo = (const float*)d_in[17];
    const float* ln1g = (const float*)d_in[18]; const float* ln1b = (const float*)d_in[19];
    const float* ln2g = (const float*)d_in[20]; const float* ln2b = (const float*)d_in[21];
    const float* Wf1 = (const float*)d_in[22]; const float* bf1 = (const float*)d_in[23];
    const float* Wf2 = (const float*)d_in[24]; const float* bf2 = (const float*)d_in[25];
    const float* lnfg = (const float*)d_in[26]; const float* lnfb = (const float*)d_in[27];
    const float* Wh1 = (const float*)d_in[28]; const float* bh1 = (const float*)d_in[29];
    const float* Wh2 = (const float*)d_in[30]; const float* bh2 = (const float*)d_in[31];
    float* out = (float*)d_out;

    void* p;
    cudaGetSymbolAddress(&p, g_x); float* xb = (float*)p;
    cudaGetSymbolAddress(&p, g_q); float* qb = (float*)p;
    cudaGetSymbolAddress(&p, g_k); float* kb = (float*)p;
    cudaGetSymbolAddress(&p, g_v); float* vb = (float*)p;
    cudaGetSymbolAddress(&p, g_a); float* ab = (float*)p;
    cudaGetSymbolAddress(&p, g_t); float* tb = (float*)p;
    cudaGetSymbolAddress(&p, g_h); float* hb = (float*)p;

    embed_kernel<<<MTOK, 256>>>(cf, xc, yc, Wemb, bemb, Wct1, bct1, Wct2, bct2, cls);

    dim3 g256((MTOK + 127)/128, D/128);    // 65 x 2
    dim3 gff ((MTOK + 127)/128, DFF/128);  // 65 x 8
    dim3 gattn((SLEN + 127)/128, NH, BB);  // 9 x 8 x 8
    int lngrid = MTOK / 8;                 // 1025

    for (int l = 0; l < NL; l++) {
        size_t wo = (size_t)l*D*D;
        gemm_kernel<<<g256, 256>>>(xb, Wq + wo, bq + l*D, qb, MTOK, D, D, 0);
        gemm_kernel<<<g256, 256>>>(xb, Wk + wo, bk + l*D, kb, MTOK, D, D, 0);
        gemm_kernel<<<g256, 256>>>(xb, Wv + wo, bv + l*D, vb, MTOK, D, D, 0);
        attn_kernel<<<gattn, 256>>>();
        gemm_kernel<<<g256, 256>>>(ab, Wo + wo, bo + l*D, tb, MTOK, D, D, 0);
        ln_kernel<<<lngrid, 256>>>(xb, tb, ln1g + l*D, ln1b + l*D, xb);
        gemm_kernel<<<gff, 256>>>(xb, Wf1 + (size_t)l*D*DFF, bf1 + l*DFF, hb, MTOK, DFF, D, 1);
        gemm_kernel<<<g256, 256>>>(hb, Wf2 + (size_t)l*DFF*D, bf2 + l*D, tb, MTOK, D, DFF, 0);
        ln_kernel<<<lngrid, 256>>>(xb, tb, ln2g + l*D, ln2b + l*D, xb);
    }

    head_kernel<<<BB, 256>>>(lnfg, lnfb, Wh1, bh1, Wh2, bh2, out);
}